// round 10
// baseline (speedup 1.0000x reference)
#include <cuda_runtime.h>
#include <cstdint>

#define N_NODES 50000
#define N_EDGES 600000
#define D_K     128
#define D_H1    128
#define D_H2    64

// ---------------- scratch (device globals: no allocation allowed) ----------
// g_deg is zero at module load and re-zeroed by k_scan each run (invariant).
__device__ int   g_deg     [N_NODES];
__device__ float g_dinv    [N_NODES];
__device__ int   g_rowstart[N_NODES + 1];
__device__ int   g_cursor  [N_NODES];
__device__ int   g_csr_src [N_EDGES];
__device__ __align__(16) float g_t1  [N_NODES * D_H1];   // (x @ W1) * dinv[row]
__device__ __align__(16) float g_agg1[N_NODES * D_H1];   // aggregated layer-1
__device__ __align__(16) float g_t2  [N_NODES * D_H2];   // (relu(agg1+b1) @ W2) * dinv[row]

__device__ __forceinline__ int clampi(int v) {
    return min(max(v, 0), N_NODES - 1);
}

// ---------------- degree count (into zeroed g_deg) --------------------------
__global__ void k_count_deg(const int* __restrict__ ei) {
    int e = blockIdx.x * blockDim.x + threadIdx.x;
    if (e < N_EDGES) atomicAdd(&g_deg[clampi(ei[N_EDGES + e])], 1);  // dst
}

// ---------------- single-block scan: rowstart/cursor/dinv, re-zero deg ------
__global__ void __launch_bounds__(1024) k_scan() {
    __shared__ int s[1024];
    const int T = 1024;
    const int C = (N_NODES + T - 1) / T;    // 49
    int t = threadIdx.x;
    int base = t * C;

    int sum = 0;
    for (int i = 0; i < C; i++) {
        int n = base + i;
        if (n < N_NODES) sum += g_deg[n];
    }
    s[t] = sum;
    __syncthreads();
    for (int off = 1; off < T; off <<= 1) {
        int add = (t >= off) ? s[t - off] : 0;
        __syncthreads();
        s[t] += add;
        __syncthreads();
    }
    int run = s[t] - sum;                   // exclusive prefix
    for (int i = 0; i < C; i++) {
        int n = base + i;
        if (n < N_NODES) {
            int d = g_deg[n];
            g_rowstart[n] = run;
            g_cursor[n]   = run;
            g_dinv[n]     = rsqrtf((float)(d + 1));  // +1 self-loop
            g_deg[n]      = 0;              // restore zero for next run
            run += d;
        }
    }
    if (t == T - 1) g_rowstart[N_NODES] = run;   // == N_EDGES
}

// ---------------- CSR fill (src only) ---------------------------------------
__global__ void k_fill(const int* __restrict__ ei) {
    int e = blockIdx.x * blockDim.x + threadIdx.x;
    if (e >= N_EDGES) return;
    int src = clampi(ei[e]);
    int dst = clampi(ei[N_EDGES + e]);
    int pos = atomicAdd(&g_cursor[dst], 1);
    g_csr_src[pos] = src;
}

// ---------------- tensor-core GEMM (3xTF32): T = (f(A) @ W) * dinv[row] -----
__device__ __forceinline__ unsigned f2tf32(float x) {
    unsigned r;
    asm("cvt.rna.tf32.f32 %0, %1;" : "=r"(r) : "f"(x));
    return r;
}

__device__ __forceinline__ void mma_tf32(float* d, const unsigned* a, const unsigned* b) {
    asm volatile(
        "mma.sync.aligned.m16n8k8.row.col.f32.tf32.tf32.f32 "
        "{%0,%1,%2,%3}, {%4,%5,%6,%7}, {%8,%9}, {%0,%1,%2,%3};"
        : "+f"(d[0]), "+f"(d[1]), "+f"(d[2]), "+f"(d[3])
        : "r"(a[0]), "r"(a[1]), "r"(a[2]), "r"(a[3]), "r"(b[0]), "r"(b[1]));
}

// BM=128 x BN=64 block tile, 8 warps (WM=2 x WN=4), warp tile 64x16:
// MT=4 m16-tiles, NT=2 n8-tiles, acc = 32 regs -> 2 CTAs/SM.
// A pre-split into tf32 hi/lo at staging (removes per-use cvt ALU on A side).
// blockIdx.y selects the BN-column slice of W/T (NOUT = full output width).
template<int NOUT, bool IN_TRANS>
__device__ __forceinline__ void gemm_tc_body(const float* __restrict__ A,
                                             const float* __restrict__ W,
                                             const float* __restrict__ b_in,
                                             float* __restrict__ T)
{
    constexpr int BM = 128, BN = 64, WM = 2, WN = 4;
    constexpr int KC = 32;
    constexpr int THREADS = 256;
    constexpr int MT = BM / WM / 16;          // 4
    constexpr int NT = BN / WN / 8;           // 2
    constexpr int AP = KC + 4;                // A row pad (36): reads conflict-free
    constexpr int WP = BN + 8;                // W row pad (72): reads conflict-free

    __shared__ unsigned As_hi[BM][AP];
    __shared__ unsigned As_lo[BM][AP];
    __shared__ float    Ws[KC][WP];

    const int tid   = threadIdx.x;
    const int wid   = tid >> 5;
    const int lane  = tid & 31;
    const int wm    = wid % WM;
    const int wn    = wid / WM;
    const int group = lane >> 2;              // 0..7
    const int tig   = lane & 3;               // 0..3
    const int row0  = blockIdx.x * BM;
    const int n0    = blockIdx.y * BN;        // output-column slice
    const int mbase = wm * (BM / WM);
    const int nbase = wn * (BN / WN);

    float acc[MT][NT][4];
#pragma unroll
    for (int im = 0; im < MT; im++)
#pragma unroll
        for (int in = 0; in < NT; in++)
#pragma unroll
            for (int e = 0; e < 4; e++) acc[im][in][e] = 0.f;

    for (int kc = 0; kc < D_K; kc += KC) {
        // ---- stage A chunk (BM x 32): fused relu(+b), split to tf32 hi/lo --
#pragma unroll
        for (int q = 0; q < BM * (KC / 4) / THREADS; q++) {
            int f  = tid + q * THREADS;
            int r  = f >> 3;                  // 8 float4 per row
            int k4 = f & 7;
            float4 v = make_float4(0.f, 0.f, 0.f, 0.f);
            int gr = row0 + r;
            if (gr < N_NODES)
                v = *(const float4*)&A[(size_t)gr * D_K + kc + k4 * 4];
            if constexpr (IN_TRANS) {
                float4 bb = *(const float4*)&b_in[kc + k4 * 4];
                v.x = fmaxf(v.x + bb.x, 0.f);
                v.y = fmaxf(v.y + bb.y, 0.f);
                v.z = fmaxf(v.z + bb.z, 0.f);
                v.w = fmaxf(v.w + bb.w, 0.f);
            }
            float vv[4] = {v.x, v.y, v.z, v.w};
#pragma unroll
            for (int j = 0; j < 4; j++) {
                unsigned h = f2tf32(vv[j]);
                As_hi[r][k4 * 4 + j] = h;
                As_lo[r][k4 * 4 + j] = f2tf32(vv[j] - __uint_as_float(h));
            }
        }
        // ---- stage W chunk (32 x BN slice at n0) ---------------------------
#pragma unroll
        for (int q = 0; q < KC * (BN / 4) / THREADS; q++) {
            int f  = tid + q * THREADS;
            int kk = f / (BN / 4);
            int n4 = f % (BN / 4);
            *(float4*)&Ws[kk][n4 * 4] =
                *(const float4*)&W[(size_t)(kc + kk) * NOUT + n0 + n4 * 4];
        }
        __syncthreads();

#pragma unroll
        for (int ks = 0; ks < KC / 8; ks++) {
            unsigned ah[MT][4], al[MT][4];
#pragma unroll
            for (int im = 0; im < MT; im++) {
#pragma unroll
                for (int e = 0; e < 4; e++) {
                    int r = mbase + im * 16 + group + (e & 1) * 8;
                    int k = ks * 8 + tig + (e >> 1) * 4;
                    ah[im][e] = As_hi[r][k];
                    al[im][e] = As_lo[r][k];
                }
            }
#pragma unroll
            for (int in = 0; in < NT; in++) {
                unsigned bh[2], bl[2];
#pragma unroll
                for (int e = 0; e < 2; e++) {
                    int k = ks * 8 + tig + e * 4;
                    int n = nbase + in * 8 + group;
                    float b = Ws[k][n];
                    unsigned h = f2tf32(b);
                    bh[e] = h;
                    bl[e] = f2tf32(b - __uint_as_float(h));
                }
#pragma unroll
                for (int im = 0; im < MT; im++) {
                    mma_tf32(acc[im][in], ah[im], bh);
                    mma_tf32(acc[im][in], ah[im], bl);
                    mma_tf32(acc[im][in], al[im], bh);
                }
            }
        }
        __syncthreads();
    }

    // ---- epilogue: prescale by dinv[row], store (c-fragment layout) -------
#pragma unroll
    for (int im = 0; im < MT; im++) {
#pragma unroll
        for (int half = 0; half < 2; half++) {
            int r = row0 + mbase + im * 16 + group + half * 8;
            if (r >= N_NODES) continue;
            float dv = g_dinv[r];
#pragma unroll
            for (int in = 0; in < NT; in++) {
                float2 t;
                t.x = acc[im][in][half * 2 + 0] * dv;
                t.y = acc[im][in][half * 2 + 1] * dv;
                *(float2*)&T[(size_t)r * NOUT + n0 + nbase + in * 8 + 2 * tig] = t;
            }
        }
    }
}

__global__ void __launch_bounds__(256, 2)
k_gemm1(const float* __restrict__ x, const float* __restrict__ W1) {
    gemm_tc_body<D_H1, false>(x, W1, nullptr, g_t1);
}

__global__ void __launch_bounds__(256, 2)
k_gemm2(const float* __restrict__ W2, const float* __restrict__ b1) {
    gemm_tc_body<D_H2, true>(g_agg1, W2, b1, g_t2);
}

// ---------------- layer-1 aggregate: gather, warp per node, MLP=2 -----------
__global__ void k_agg1() {
    int n    = (blockIdx.x * blockDim.x + threadIdx.x) >> 5;
    int lane = threadIdx.x & 31;
    if (n >= N_NODES) return;

    int   s0 = g_rowstart[n];
    int   s1 = g_rowstart[n + 1];
    float dv = g_dinv[n];

    float4 acc = *(const float4*)&g_t1[(size_t)n * D_H1 + lane * 4];

    int e = s0;
    for (; e + 1 < s1; e += 2) {
        int srcA = g_csr_src[e];
        int srcB = g_csr_src[e + 1];
        float4 vA = *(const float4*)&g_t1[(size_t)srcA * D_H1 + lane * 4];
        float4 vB = *(const float4*)&g_t1[(size_t)srcB * D_H1 + lane * 4];
        acc.x += vA.x + vB.x;
        acc.y += vA.y + vB.y;
        acc.z += vA.z + vB.z;
        acc.w += vA.w + vB.w;
    }
    if (e < s1) {
        int src = g_csr_src[e];
        float4 v = *(const float4*)&g_t1[(size_t)src * D_H1 + lane * 4];
        acc.x += v.x; acc.y += v.y; acc.z += v.z; acc.w += v.w;
    }
    acc.x *= dv; acc.y *= dv; acc.z *= dv; acc.w *= dv;
    *(float4*)&g_agg1[(size_t)n * D_H1 + lane * 4] = acc;
}

// ---------------- layer-2 aggregate fused with final GEMV, MLP=2 ------------
__global__ void k_agg2_final(const float* __restrict__ b2,
                             const float* __restrict__ W3,
                             const float* __restrict__ b3,
                             float* __restrict__ out)
{
    int n    = (blockIdx.x * blockDim.x + threadIdx.x) >> 5;
    int lane = threadIdx.x & 31;
    if (n >= N_NODES) return;

    int   s0 = g_rowstart[n];
    int   s1 = g_rowstart[n + 1];
    float dv = g_dinv[n];

    float2 acc = *(const float2*)&g_t2[(size_t)n * D_H2 + lane * 2];

    int e = s0;
    for (; e + 1 < s1; e += 2) {
        int srcA = g_csr_src[e];
        int srcB = g_csr_src[e + 1];
        float2 vA = *(const float2*)&g_t2[(size_t)srcA * D_H2 + lane * 2];
        float2 vB = *(const float2*)&g_t2[(size_t)srcB * D_H2 + lane * 2];
        acc.x += vA.x + vB.x;
        acc.y += vA.y + vB.y;
    }
    if (e < s1) {
        int src = g_csr_src[e];
        float2 v = *(const float2*)&g_t2[(size_t)src * D_H2 + lane * 2];
        acc.x += v.x; acc.y += v.y;
    }
    acc.x *= dv; acc.y *= dv;

    float2 bb = *(const float2*)&b2[lane * 2];
    float2 w  = *(const float2*)&W3[lane * 2];
    float h0 = fmaxf(acc.x + bb.x, 0.f);
    float h1 = fmaxf(acc.y + bb.y, 0.f);
    float s  = fmaf(h0, w.x, h1 * w.y);
#pragma unroll
    for (int o = 16; o; o >>= 1) s += __shfl_xor_sync(0xffffffffu, s, o);
    if (lane == 0) out[n] = s + b3[0];
}

// ---------------- launch (single stream; gemm1 at profiled slot #4) ---------
extern "C" void kernel_launch(void* const* d_in, const int* in_sizes, int n_in,
                              void* d_out, int out_size)
{
    const float* x  = (const float*)d_in[0];
    const int*   ei = (const int*)d_in[1];     // int32 edge_index
    const float* W1 = (const float*)d_in[2];
    const float* b1 = (const float*)d_in[3];
    const float* W2 = (const float*)d_in[4];
    const float* b2 = (const float*)d_in[5];
    const float* W3 = (const float*)d_in[6];
    const float* b3 = (const float*)d_in[7];
    float*       out = (float*)d_out;
    (void)in_sizes; (void)n_in; (void)out_size;

    k_count_deg<<<(N_EDGES + 255) / 256, 256>>>(ei);
    k_scan     <<<1, 1024>>>();
    k_fill     <<<(N_EDGES + 255) / 256, 256>>>(ei);

    dim3 g1((N_NODES + 127) / 128, D_H1 / 64);
    k_gemm1<<<g1, 256>>>(x, W1);                           // slot #4
    k_agg1 <<<(N_NODES * 32 + 255) / 256, 256>>>();

    dim3 g2((N_NODES + 127) / 128, D_H2 / 64);
    k_gemm2<<<g2, 256>>>(W2, b1);
    k_agg2_final<<<(N_NODES * 32 + 255) / 256, 256>>>(b2, W3, b3, out);
}

// round 12
// speedup vs baseline: 1.0273x; 1.0273x over previous
#include <cuda_runtime.h>
#include <cstdint>

#define N_NODES 50000
#define N_EDGES 600000
#define D_K     128
#define D_H1    128
#define D_H2    64

// ---------------- scratch (device globals: no allocation allowed) ----------
// g_deg is zero at module load and re-zeroed by k_scan each run (invariant).
__device__ int   g_deg     [N_NODES];
__device__ float g_dinv    [N_NODES];
__device__ int   g_rowstart[N_NODES + 1];
__device__ int   g_cursor  [N_NODES];
__device__ int   g_csr_src [N_EDGES];
__device__ __align__(16) float g_t1  [N_NODES * D_H1];   // (x @ W1) * dinv[row]
__device__ __align__(16) float g_agg1[N_NODES * D_H1];   // aggregated layer-1
__device__ __align__(16) float g_t2  [N_NODES * D_H2];   // (relu(agg1+b1) @ W2) * dinv[row]

__device__ __forceinline__ int clampi(int v) {
    return min(max(v, 0), N_NODES - 1);
}

// ---------------- degree count (into zeroed g_deg) --------------------------
__global__ void k_count_deg(const int* __restrict__ ei) {
    int e = blockIdx.x * blockDim.x + threadIdx.x;
    if (e < N_EDGES) atomicAdd(&g_deg[clampi(ei[N_EDGES + e])], 1);  // dst
}

// ---------------- single-block scan: rowstart/cursor/dinv, re-zero deg ------
__global__ void __launch_bounds__(1024) k_scan() {
    __shared__ int s[1024];
    const int T = 1024;
    const int C = (N_NODES + T - 1) / T;    // 49
    int t = threadIdx.x;
    int base = t * C;

    int sum = 0;
    for (int i = 0; i < C; i++) {
        int n = base + i;
        if (n < N_NODES) sum += g_deg[n];
    }
    s[t] = sum;
    __syncthreads();
    for (int off = 1; off < T; off <<= 1) {
        int add = (t >= off) ? s[t - off] : 0;
        __syncthreads();
        s[t] += add;
        __syncthreads();
    }
    int run = s[t] - sum;                   // exclusive prefix
    for (int i = 0; i < C; i++) {
        int n = base + i;
        if (n < N_NODES) {
            int d = g_deg[n];
            g_rowstart[n] = run;
            g_cursor[n]   = run;
            g_dinv[n]     = rsqrtf((float)(d + 1));  // +1 self-loop
            g_deg[n]      = 0;              // restore zero for next run
            run += d;
        }
    }
    if (t == T - 1) g_rowstart[N_NODES] = run;   // == N_EDGES
}

// ---------------- tensor-core GEMM (3xTF32): T = (f(A) @ W) * dinv[row] -----
__device__ __forceinline__ unsigned f2tf32(float x) {
    unsigned r;
    asm("cvt.rna.tf32.f32 %0, %1;" : "=r"(r) : "f"(x));
    return r;
}

__device__ __forceinline__ void mma_tf32(float* d, const unsigned* a, const unsigned* b) {
    asm volatile(
        "mma.sync.aligned.m16n8k8.row.col.f32.tf32.tf32.f32 "
        "{%0,%1,%2,%3}, {%4,%5,%6,%7}, {%8,%9}, {%0,%1,%2,%3};"
        : "+f"(d[0]), "+f"(d[1]), "+f"(d[2]), "+f"(d[3])
        : "r"(a[0]), "r"(a[1]), "r"(a[2]), "r"(a[3]), "r"(b[0]), "r"(b[1]));
}

// BM=128 x BN=64 block tile, 8 warps (WM=2 x WN=4), warp tile 64x16.
// A pre-split into tf32 hi/lo at staging. bx/by passed explicitly so the
// caller can flatten/fuse grids.
template<int NOUT, bool IN_TRANS>
__device__ __forceinline__ void gemm_tc_body(const float* __restrict__ A,
                                             const float* __restrict__ W,
                                             const float* __restrict__ b_in,
                                             float* __restrict__ T,
                                             int bx, int by)
{
    constexpr int BM = 128, BN = 64, WM = 2, WN = 4;
    constexpr int KC = 32;
    constexpr int THREADS = 256;
    constexpr int MT = BM / WM / 16;          // 4
    constexpr int NT = BN / WN / 8;           // 2
    constexpr int AP = KC + 4;                // A row pad (36)
    constexpr int WP = BN + 8;                // W row pad (72)

    __shared__ unsigned As_hi[BM][AP];
    __shared__ unsigned As_lo[BM][AP];
    __shared__ float    Ws[KC][WP];

    const int tid   = threadIdx.x;
    const int wid   = tid >> 5;
    const int lane  = tid & 31;
    const int wm    = wid % WM;
    const int wn    = wid / WM;
    const int group = lane >> 2;              // 0..7
    const int tig   = lane & 3;               // 0..3
    const int row0  = bx * BM;
    const int n0    = by * BN;                // output-column slice
    const int mbase = wm * (BM / WM);
    const int nbase = wn * (BN / WN);

    float acc[MT][NT][4];
#pragma unroll
    for (int im = 0; im < MT; im++)
#pragma unroll
        for (int in = 0; in < NT; in++)
#pragma unroll
            for (int e = 0; e < 4; e++) acc[im][in][e] = 0.f;

    for (int kc = 0; kc < D_K; kc += KC) {
        // ---- stage A chunk (BM x 32): fused relu(+b), split to tf32 hi/lo --
#pragma unroll
        for (int q = 0; q < BM * (KC / 4) / THREADS; q++) {
            int f  = tid + q * THREADS;
            int r  = f >> 3;                  // 8 float4 per row
            int k4 = f & 7;
            float4 v = make_float4(0.f, 0.f, 0.f, 0.f);
            int gr = row0 + r;
            if (gr < N_NODES)
                v = *(const float4*)&A[(size_t)gr * D_K + kc + k4 * 4];
            if constexpr (IN_TRANS) {
                float4 bb = *(const float4*)&b_in[kc + k4 * 4];
                v.x = fmaxf(v.x + bb.x, 0.f);
                v.y = fmaxf(v.y + bb.y, 0.f);
                v.z = fmaxf(v.z + bb.z, 0.f);
                v.w = fmaxf(v.w + bb.w, 0.f);
            }
            float vv[4] = {v.x, v.y, v.z, v.w};
#pragma unroll
            for (int j = 0; j < 4; j++) {
                unsigned h = f2tf32(vv[j]);
                As_hi[r][k4 * 4 + j] = h;
                As_lo[r][k4 * 4 + j] = f2tf32(vv[j] - __uint_as_float(h));
            }
        }
        // ---- stage W chunk (32 x BN slice at n0) ---------------------------
#pragma unroll
        for (int q = 0; q < KC * (BN / 4) / THREADS; q++) {
            int f  = tid + q * THREADS;
            int kk = f / (BN / 4);
            int n4 = f % (BN / 4);
            *(float4*)&Ws[kk][n4 * 4] =
                *(const float4*)&W[(size_t)(kc + kk) * NOUT + n0 + n4 * 4];
        }
        __syncthreads();

#pragma unroll
        for (int ks = 0; ks < KC / 8; ks++) {
            unsigned ah[MT][4], al[MT][4];
#pragma unroll
            for (int im = 0; im < MT; im++) {
#pragma unroll
                for (int e = 0; e < 4; e++) {
                    int r = mbase + im * 16 + group + (e & 1) * 8;
                    int k = ks * 8 + tig + (e >> 1) * 4;
                    ah[im][e] = As_hi[r][k];
                    al[im][e] = As_lo[r][k];
                }
            }
#pragma unroll
            for (int in = 0; in < NT; in++) {
                unsigned bh[2], bl[2];
#pragma unroll
                for (int e = 0; e < 2; e++) {
                    int k = ks * 8 + tig + e * 4;
                    int n = nbase + in * 8 + group;
                    float b = Ws[k][n];
                    unsigned h = f2tf32(b);
                    bh[e] = h;
                    bl[e] = f2tf32(b - __uint_as_float(h));
                }
#pragma unroll
                for (int im = 0; im < MT; im++) {
                    mma_tf32(acc[im][in], ah[im], bh);
                    mma_tf32(acc[im][in], ah[im], bl);
                    mma_tf32(acc[im][in], al[im], bh);
                }
            }
        }
        __syncthreads();
    }

    // ---- epilogue: prescale by dinv[row], store (c-fragment layout) -------
#pragma unroll
    for (int im = 0; im < MT; im++) {
#pragma unroll
        for (int half = 0; half < 2; half++) {
            int r = row0 + mbase + im * 16 + group + half * 8;
            if (r >= N_NODES) continue;
            float dv = g_dinv[r];
#pragma unroll
            for (int in = 0; in < NT; in++) {
                float2 t;
                t.x = acc[im][in][half * 2 + 0] * dv;
                t.y = acc[im][in][half * 2 + 1] * dv;
                *(float2*)&T[(size_t)r * NOUT + n0 + nbase + in * 8 + 2 * tig] = t;
            }
        }
    }
}

// ---------------- fused: gemm1 tiles + CSR fill in one launch ---------------
// Both depend only on k_scan (gemm1 reads dinv; fill reads cursor), and are
// mutually independent. Blocks [0, G1) run gemm1; blocks [G1, G1+FB) run fill.
#define G1_BLOCKS  ((N_NODES + 127) / 128 * 2)         // 782
#define FILL_BLOCKS ((N_EDGES + 255) / 256)            // 2344

__global__ void __launch_bounds__(256, 2)
k_gemm1_fill(const float* __restrict__ x, const float* __restrict__ W1,
             const int* __restrict__ ei)
{
    int b = blockIdx.x;
    if (b < G1_BLOCKS) {
        gemm_tc_body<D_H1, false>(x, W1, nullptr, g_t1, b >> 1, b & 1);
    } else {
        int e = (b - G1_BLOCKS) * 256 + threadIdx.x;
        if (e < N_EDGES) {
            int src = clampi(ei[e]);
            int dst = clampi(ei[N_EDGES + e]);
            int pos = atomicAdd(&g_cursor[dst], 1);
            g_csr_src[pos] = src;
        }
    }
}

__global__ void __launch_bounds__(256, 2)
k_gemm2(const float* __restrict__ W2, const float* __restrict__ b1) {
    gemm_tc_body<D_H2, true>(g_agg1, W2, b1, g_t2, blockIdx.x, 0);
}

// ---------------- layer-1 aggregate: gather, warp per node, MLP=2 -----------
__global__ void k_agg1() {
    int n    = (blockIdx.x * blockDim.x + threadIdx.x) >> 5;
    int lane = threadIdx.x & 31;
    if (n >= N_NODES) return;

    int   s0 = g_rowstart[n];
    int   s1 = g_rowstart[n + 1];
    float dv = g_dinv[n];

    float4 acc = *(const float4*)&g_t1[(size_t)n * D_H1 + lane * 4];

    int e = s0;
    for (; e + 1 < s1; e += 2) {
        int srcA = g_csr_src[e];
        int srcB = g_csr_src[e + 1];
        float4 vA = *(const float4*)&g_t1[(size_t)srcA * D_H1 + lane * 4];
        float4 vB = *(const float4*)&g_t1[(size_t)srcB * D_H1 + lane * 4];
        acc.x += vA.x + vB.x;
        acc.y += vA.y + vB.y;
        acc.z += vA.z + vB.z;
        acc.w += vA.w + vB.w;
    }
    if (e < s1) {
        int src = g_csr_src[e];
        float4 v = *(const float4*)&g_t1[(size_t)src * D_H1 + lane * 4];
        acc.x += v.x; acc.y += v.y; acc.z += v.z; acc.w += v.w;
    }
    acc.x *= dv; acc.y *= dv; acc.z *= dv; acc.w *= dv;
    *(float4*)&g_agg1[(size_t)n * D_H1 + lane * 4] = acc;
}

// ---------------- layer-2 aggregate fused with final GEMV, MLP=2 ------------
__global__ void k_agg2_final(const float* __restrict__ b2,
                             const float* __restrict__ W3,
                             const float* __restrict__ b3,
                             float* __restrict__ out)
{
    int n    = (blockIdx.x * blockDim.x + threadIdx.x) >> 5;
    int lane = threadIdx.x & 31;
    if (n >= N_NODES) return;

    int   s0 = g_rowstart[n];
    int   s1 = g_rowstart[n + 1];
    float dv = g_dinv[n];

    float2 acc = *(const float2*)&g_t2[(size_t)n * D_H2 + lane * 2];

    int e = s0;
    for (; e + 1 < s1; e += 2) {
        int srcA = g_csr_src[e];
        int srcB = g_csr_src[e + 1];
        float2 vA = *(const float2*)&g_t2[(size_t)srcA * D_H2 + lane * 2];
        float2 vB = *(const float2*)&g_t2[(size_t)srcB * D_H2 + lane * 2];
        acc.x += vA.x + vB.x;
        acc.y += vA.y + vB.y;
    }
    if (e < s1) {
        int src = g_csr_src[e];
        float2 v = *(const float2*)&g_t2[(size_t)src * D_H2 + lane * 2];
        acc.x += v.x; acc.y += v.y;
    }
    acc.x *= dv; acc.y *= dv;

    float2 bb = *(const float2*)&b2[lane * 2];
    float2 w  = *(const float2*)&W3[lane * 2];
    float h0 = fmaxf(acc.x + bb.x, 0.f);
    float h1 = fmaxf(acc.y + bb.y, 0.f);
    float s  = fmaf(h0, w.x, h1 * w.y);
#pragma unroll
    for (int o = 16; o; o >>= 1) s += __shfl_xor_sync(0xffffffffu, s, o);
    if (lane == 0) out[n] = s + b3[0];
}

// ---------------- launch (single stream; agg1 at profiled slot #4) ----------
extern "C" void kernel_launch(void* const* d_in, const int* in_sizes, int n_in,
                              void* d_out, int out_size)
{
    const float* x  = (const float*)d_in[0];
    const int*   ei = (const int*)d_in[1];     // int32 edge_index
    const float* W1 = (const float*)d_in[2];
    const float* b1 = (const float*)d_in[3];
    const float* W2 = (const float*)d_in[4];
    const float* b2 = (const float*)d_in[5];
    const float* W3 = (const float*)d_in[6];
    const float* b3 = (const float*)d_in[7];
    float*       out = (float*)d_out;
    (void)in_sizes; (void)n_in; (void)out_size;

    k_count_deg <<<(N_EDGES + 255) / 256, 256>>>(ei);            // slot 1
    k_scan      <<<1, 1024>>>();                                 // slot 2
    k_gemm1_fill<<<G1_BLOCKS + FILL_BLOCKS, 256>>>(x, W1, ei);   // slot 3
    k_agg1      <<<(N_NODES * 32 + 255) / 256, 256>>>();         // slot 4 (profiled)
    k_gemm2     <<<(N_NODES + 127) / 128, 256>>>(W2, b1);        // slot 5
    k_agg2_final<<<(N_NODES * 32 + 255) / 256, 256>>>(b2, W3, b3, out);
}

// round 13
// speedup vs baseline: 1.8697x; 1.8200x over previous
#include <cuda_runtime.h>
#include <cstdint>

#define N_NODES 50000
#define N_EDGES 600000
#define D_K     128
#define D_H1    128
#define D_H2    64

#define SCAN_NB ((N_NODES + 255) / 256)                // 196

// ---------------- scratch (device globals: no allocation allowed) ----------
// g_deg is zero at module load and re-zeroed by k_scanC each run (invariant).
__device__ int   g_deg     [N_NODES];
__device__ float g_dinv    [N_NODES];
__device__ int   g_bsum    [SCAN_NB];
__device__ int   g_rowstart[N_NODES + 1];
__device__ int   g_cursor  [N_NODES];
__device__ int   g_csr_src [N_EDGES];
__device__ __align__(16) float g_t1  [N_NODES * D_H1];   // x @ W1 (RAW, no prescale)
__device__ __align__(16) float g_agg1[N_NODES * D_H1];   // aggregated layer-1
__device__ __align__(16) float g_t2  [N_NODES * D_H2];   // (relu(agg1+b1) @ W2) * dinv[row]

__device__ __forceinline__ int clampi(int v) {
    return min(max(v, 0), N_NODES - 1);
}

// ---------------- tensor-core GEMM (3xTF32) ---------------------------------
__device__ __forceinline__ unsigned f2tf32(float x) {
    unsigned r;
    asm("cvt.rna.tf32.f32 %0, %1;" : "=r"(r) : "f"(x));
    return r;
}

__device__ __forceinline__ void mma_tf32(float* d, const unsigned* a, const unsigned* b) {
    asm volatile(
        "mma.sync.aligned.m16n8k8.row.col.f32.tf32.tf32.f32 "
        "{%0,%1,%2,%3}, {%4,%5,%6,%7}, {%8,%9}, {%0,%1,%2,%3};"
        : "+f"(d[0]), "+f"(d[1]), "+f"(d[2]), "+f"(d[3])
        : "r"(a[0]), "r"(a[1]), "r"(a[2]), "r"(a[3]), "r"(b[0]), "r"(b[1]));
}

// BM=128 x BN=64 block tile, 8 warps (WM=2 x WN=4), warp tile 64x16.
// PRESCALE: multiply output rows by dinv[row] (requires dinv ready!).
template<int NOUT, bool IN_TRANS, bool PRESCALE>
__device__ __forceinline__ void gemm_tc_body(const float* __restrict__ A,
                                             const float* __restrict__ W,
                                             const float* __restrict__ b_in,
                                             float* __restrict__ T,
                                             int bx, int by)
{
    constexpr int BM = 128, BN = 64, WM = 2, WN = 4;
    constexpr int KC = 32;
    constexpr int THREADS = 256;
    constexpr int MT = BM / WM / 16;          // 4
    constexpr int NT = BN / WN / 8;           // 2
    constexpr int AP = KC + 4;                // A row pad (36)
    constexpr int WP = BN + 8;                // W row pad (72)

    __shared__ unsigned As_hi[BM][AP];
    __shared__ unsigned As_lo[BM][AP];
    __shared__ float    Ws[KC][WP];

    const int tid   = threadIdx.x;
    const int wid   = tid >> 5;
    const int lane  = tid & 31;
    const int wm    = wid % WM;
    const int wn    = wid / WM;
    const int group = lane >> 2;              // 0..7
    const int tig   = lane & 3;               // 0..3
    const int row0  = bx * BM;
    const int n0    = by * BN;                // output-column slice
    const int mbase = wm * (BM / WM);
    const int nbase = wn * (BN / WN);

    float acc[MT][NT][4];
#pragma unroll
    for (int im = 0; im < MT; im++)
#pragma unroll
        for (int in = 0; in < NT; in++)
#pragma unroll
            for (int e = 0; e < 4; e++) acc[im][in][e] = 0.f;

    for (int kc = 0; kc < D_K; kc += KC) {
        // ---- stage A chunk (BM x 32): fused relu(+b), split to tf32 hi/lo --
#pragma unroll
        for (int q = 0; q < BM * (KC / 4) / THREADS; q++) {
            int f  = tid + q * THREADS;
            int r  = f >> 3;                  // 8 float4 per row
            int k4 = f & 7;
            float4 v = make_float4(0.f, 0.f, 0.f, 0.f);
            int gr = row0 + r;
            if (gr < N_NODES)
                v = *(const float4*)&A[(size_t)gr * D_K + kc + k4 * 4];
            if constexpr (IN_TRANS) {
                float4 bb = *(const float4*)&b_in[kc + k4 * 4];
                v.x = fmaxf(v.x + bb.x, 0.f);
                v.y = fmaxf(v.y + bb.y, 0.f);
                v.z = fmaxf(v.z + bb.z, 0.f);
                v.w = fmaxf(v.w + bb.w, 0.f);
            }
            float vv[4] = {v.x, v.y, v.z, v.w};
#pragma unroll
            for (int j = 0; j < 4; j++) {
                unsigned h = f2tf32(vv[j]);
                As_hi[r][k4 * 4 + j] = h;
                As_lo[r][k4 * 4 + j] = f2tf32(vv[j] - __uint_as_float(h));
            }
        }
        // ---- stage W chunk (32 x BN slice at n0) ---------------------------
#pragma unroll
        for (int q = 0; q < KC * (BN / 4) / THREADS; q++) {
            int f  = tid + q * THREADS;
            int kk = f / (BN / 4);
            int n4 = f % (BN / 4);
            *(float4*)&Ws[kk][n4 * 4] =
                *(const float4*)&W[(size_t)(kc + kk) * NOUT + n0 + n4 * 4];
        }
        __syncthreads();

#pragma unroll
        for (int ks = 0; ks < KC / 8; ks++) {
            unsigned ah[MT][4], al[MT][4];
#pragma unroll
            for (int im = 0; im < MT; im++) {
#pragma unroll
                for (int e = 0; e < 4; e++) {
                    int r = mbase + im * 16 + group + (e & 1) * 8;
                    int k = ks * 8 + tig + (e >> 1) * 4;
                    ah[im][e] = As_hi[r][k];
                    al[im][e] = As_lo[r][k];
                }
            }
#pragma unroll
            for (int in = 0; in < NT; in++) {
                unsigned bh[2], bl[2];
#pragma unroll
                for (int e = 0; e < 2; e++) {
                    int k = ks * 8 + tig + e * 4;
                    int n = nbase + in * 8 + group;
                    float b = Ws[k][n];
                    unsigned h = f2tf32(b);
                    bh[e] = h;
                    bl[e] = f2tf32(b - __uint_as_float(h));
                }
#pragma unroll
                for (int im = 0; im < MT; im++) {
                    mma_tf32(acc[im][in], ah[im], bh);
                    mma_tf32(acc[im][in], ah[im], bl);
                    mma_tf32(acc[im][in], al[im], bh);
                }
            }
        }
        __syncthreads();
    }

    // ---- epilogue: optional dinv[row] prescale, store ----------------------
#pragma unroll
    for (int im = 0; im < MT; im++) {
#pragma unroll
        for (int half = 0; half < 2; half++) {
            int r = row0 + mbase + im * 16 + group + half * 8;
            if (r >= N_NODES) continue;
            float dv = PRESCALE ? g_dinv[r] : 1.0f;
#pragma unroll
            for (int in = 0; in < NT; in++) {
                float2 t;
                t.x = acc[im][in][half * 2 + 0] * dv;
                t.y = acc[im][in][half * 2 + 1] * dv;
                *(float2*)&T[(size_t)r * NOUT + n0 + nbase + in * 8 + 2 * tig] = t;
            }
        }
    }
}

// ---------------- fused: gemm1 (raw output) + degree count ------------------
// gemm1 no longer reads dinv (raw t1), so it depends on nothing but inputs;
// count rides in the same launch. Legal R11 redux.
#define G1_BLOCKS  ((N_NODES + 127) / 128 * 2)         // 782
#define CNT_BLOCKS ((N_EDGES + 255) / 256)             // 2344

__global__ void __launch_bounds__(256, 2)
k_gemm1_count(const float* __restrict__ x, const float* __restrict__ W1,
              const int* __restrict__ ei)
{
    int b = blockIdx.x;
    if (b < G1_BLOCKS) {
        gemm_tc_body<D_H1, false, false>(x, W1, nullptr, g_t1, b >> 1, b & 1);
    } else {
        int e = (b - G1_BLOCKS) * 256 + threadIdx.x;
        if (e < N_EDGES) atomicAdd(&g_deg[clampi(ei[N_EDGES + e])], 1);
    }
}

__global__ void __launch_bounds__(256, 2)
k_gemm2(const float* __restrict__ W2, const float* __restrict__ b1) {
    gemm_tc_body<D_H2, true, true>(g_agg1, W2, b1, g_t2, blockIdx.x, 0);
}

// ---------------- parallel 3-phase scan --------------------------------------
__global__ void k_scanA() {
    __shared__ int sh[256];
    int t = threadIdx.x;
    int n = blockIdx.x * 256 + t;
    sh[t] = (n < N_NODES) ? g_deg[n] : 0;
    __syncthreads();
#pragma unroll
    for (int off = 128; off; off >>= 1) {
        if (t < off) sh[t] += sh[t + off];
        __syncthreads();
    }
    if (t == 0) g_bsum[blockIdx.x] = sh[0];
}

__global__ void k_scanB() {
    __shared__ int sh[256];
    int t = threadIdx.x;
    int v = (t < SCAN_NB) ? g_bsum[t] : 0;
    sh[t] = v;
    __syncthreads();
    for (int off = 1; off < 256; off <<= 1) {
        int add = (t >= off) ? sh[t - off] : 0;
        __syncthreads();
        sh[t] += add;
        __syncthreads();
    }
    if (t < SCAN_NB) g_bsum[t] = sh[t] - v;            // exclusive
    if (t == 255) g_rowstart[N_NODES] = sh[255];       // total == N_EDGES
}

__global__ void k_scanC() {
    __shared__ int sh[256];
    int t = threadIdx.x;
    int n = blockIdx.x * 256 + t;
    int d = (n < N_NODES) ? g_deg[n] : 0;
    sh[t] = d;
    __syncthreads();
    for (int off = 1; off < 256; off <<= 1) {
        int add = (t >= off) ? sh[t - off] : 0;
        __syncthreads();
        sh[t] += add;
        __syncthreads();
    }
    if (n < N_NODES) {
        int run = g_bsum[blockIdx.x] + sh[t] - d;      // exclusive prefix
        g_rowstart[n] = run;
        g_cursor[n]   = run;
        g_dinv[n]     = rsqrtf((float)(d + 1));        // +1 self-loop
        g_deg[n]      = 0;                             // restore zero
    }
}

// ---------------- CSR fill (src only) ---------------------------------------
__global__ void k_fill(const int* __restrict__ ei) {
    int e = blockIdx.x * blockDim.x + threadIdx.x;
    if (e >= N_EDGES) return;
    int src = clampi(ei[e]);
    int dst = clampi(ei[N_EDGES + e]);
    int pos = atomicAdd(&g_cursor[dst], 1);
    g_csr_src[pos] = src;
}

// ---------------- layer-1 aggregate: t1 raw, per-edge dinv[src] -------------
// agg1[n] = dinv[n] * ( t1[n]*dinv[n] + sum_e t1[src_e]*dinv[src_e] )
__global__ void k_agg1() {
    int n    = (blockIdx.x * blockDim.x + threadIdx.x) >> 5;
    int lane = threadIdx.x & 31;
    if (n >= N_NODES) return;

    int   s0 = g_rowstart[n];
    int   s1 = g_rowstart[n + 1];
    float dv = g_dinv[n];

    float4 acc = *(const float4*)&g_t1[(size_t)n * D_H1 + lane * 4];
    acc.x *= dv; acc.y *= dv; acc.z *= dv; acc.w *= dv;

    int e = s0;
    for (; e + 1 < s1; e += 2) {
        int srcA = g_csr_src[e];
        int srcB = g_csr_src[e + 1];
        float nmA = g_dinv[srcA];              // broadcast
        float nmB = g_dinv[srcB];
        float4 vA = *(const float4*)&g_t1[(size_t)srcA * D_H1 + lane * 4];
        float4 vB = *(const float4*)&g_t1[(size_t)srcB * D_H1 + lane * 4];
        acc.x = fmaf(vA.x, nmA, acc.x);
        acc.y = fmaf(vA.y, nmA, acc.y);
        acc.z = fmaf(vA.z, nmA, acc.z);
        acc.w = fmaf(vA.w, nmA, acc.w);
        acc.x = fmaf(vB.x, nmB, acc.x);
        acc.y = fmaf(vB.y, nmB, acc.y);
        acc.z = fmaf(vB.z, nmB, acc.z);
        acc.w = fmaf(vB.w, nmB, acc.w);
    }
    if (e < s1) {
        int src = g_csr_src[e];
        float nm = g_dinv[src];
        float4 v = *(const float4*)&g_t1[(size_t)src * D_H1 + lane * 4];
        acc.x = fmaf(v.x, nm, acc.x);
        acc.y = fmaf(v.y, nm, acc.y);
        acc.z = fmaf(v.z, nm, acc.z);
        acc.w = fmaf(v.w, nm, acc.w);
    }
    acc.x *= dv; acc.y *= dv; acc.z *= dv; acc.w *= dv;
    *(float4*)&g_agg1[(size_t)n * D_H1 + lane * 4] = acc;
}

// ---------------- layer-2 aggregate (t2 prescaled) + final GEMV -------------
__global__ void k_agg2_final(const float* __restrict__ b2,
                             const float* __restrict__ W3,
                             const float* __restrict__ b3,
                             float* __restrict__ out)
{
    int n    = (blockIdx.x * blockDim.x + threadIdx.x) >> 5;
    int lane = threadIdx.x & 31;
    if (n >= N_NODES) return;

    int   s0 = g_rowstart[n];
    int   s1 = g_rowstart[n + 1];
    float dv = g_dinv[n];

    float2 acc = *(const float2*)&g_t2[(size_t)n * D_H2 + lane * 2];

    int e = s0;
    for (; e + 1 < s1; e += 2) {
        int srcA = g_csr_src[e];
        int srcB = g_csr_src[e + 1];
        float2 vA = *(const float2*)&g_t2[(size_t)srcA * D_H2 + lane * 2];
        float2 vB = *(const float2*)&g_t2[(size_t)srcB * D_H2 + lane * 2];
        acc.x += vA.x + vB.x;
        acc.y += vA.y + vB.y;
    }
    if (e < s1) {
        int src = g_csr_src[e];
        float2 v = *(const float2*)&g_t2[(size_t)src * D_H2 + lane * 2];
        acc.x += v.x; acc.y += v.y;
    }
    acc.x *= dv; acc.y *= dv;

    float2 bb = *(const float2*)&b2[lane * 2];
    float2 w  = *(const float2*)&W3[lane * 2];
    float h0 = fmaxf(acc.x + bb.x, 0.f);
    float h1 = fmaxf(acc.y + bb.y, 0.f);
    float s  = fmaf(h0, w.x, h1 * w.y);
#pragma unroll
    for (int o = 16; o; o >>= 1) s += __shfl_xor_sync(0xffffffffu, s, o);
    if (lane == 0) out[n] = s + b3[0];
}

// ---------------- launch (single stream) ------------------------------------
extern "C" void kernel_launch(void* const* d_in, const int* in_sizes, int n_in,
                              void* d_out, int out_size)
{
    const float* x  = (const float*)d_in[0];
    const int*   ei = (const int*)d_in[1];     // int32 edge_index
    const float* W1 = (const float*)d_in[2];
    const float* b1 = (const float*)d_in[3];
    const float* W2 = (const float*)d_in[4];
    const float* b2 = (const float*)d_in[5];
    const float* W3 = (const float*)d_in[6];
    const float* b3 = (const float*)d_in[7];
    float*       out = (float*)d_out;
    (void)in_sizes; (void)n_in; (void)out_size;

    k_gemm1_count<<<G1_BLOCKS + CNT_BLOCKS, 256>>>(x, W1, ei);  // 1
    k_scanA      <<<SCAN_NB, 256>>>();                           // 2
    k_scanB      <<<1, 256>>>();                                 // 3
    k_scanC      <<<SCAN_NB, 256>>>();                           // 4 (profiled)
    k_fill       <<<(N_EDGES + 255) / 256, 256>>>(ei);           // 5
    k_agg1       <<<(N_NODES * 32 + 255) / 256, 256>>>();        // 6
    k_gemm2      <<<(N_NODES + 127) / 128, 256>>>(W2, b1);       // 7
    k_agg2_final <<<(N_NODES * 32 + 255) / 256, 256>>>(b2, W3, b3, out);
}

// round 14
// speedup vs baseline: 2.0246x; 1.0828x over previous
#include <cuda_runtime.h>
#include <cstdint>

#define N_NODES 50000
#define N_EDGES 600000
#define D_K     128
#define D_H1    128
#define D_H2    64

#define SCAN_NB ((N_NODES + 255) / 256)                // 196

// ---------------- scratch (device globals: no allocation allowed) ----------
// g_deg is zero at module load and re-zeroed by k_scanC each run (invariant).
__device__ int   g_deg     [N_NODES];
__device__ float g_dinv    [N_NODES];
__device__ int   g_bsum    [SCAN_NB];
__device__ int   g_rowstart[N_NODES + 1];
__device__ int   g_cursor  [N_NODES];
__device__ int   g_csr_src [N_EDGES];
__device__ __align__(16) float g_t1  [N_NODES * D_H1];   // x @ W1 (raw)
__device__ __align__(16) float g_agg1[N_NODES * D_H1];   // aggregated layer-1
__device__ __align__(16) float g_t2  [N_NODES * D_H2];   // (relu(agg1+b1) @ W2) * dinv

__device__ __forceinline__ int clampi(int v) {
    return min(max(v, 0), N_NODES - 1);
}

// ---------------- tensor-core GEMM (3xTF32) helpers --------------------------
__device__ __forceinline__ unsigned f2tf32(float x) {
    unsigned r;
    asm("cvt.rna.tf32.f32 %0, %1;" : "=r"(r) : "f"(x));
    return r;
}

__device__ __forceinline__ void mma_tf32(float* d, const unsigned* a, const unsigned* b) {
    asm volatile(
        "mma.sync.aligned.m16n8k8.row.col.f32.tf32.tf32.f32 "
        "{%0,%1,%2,%3}, {%4,%5,%6,%7}, {%8,%9}, {%0,%1,%2,%3};"
        : "+f"(d[0]), "+f"(d[1]), "+f"(d[2]), "+f"(d[3])
        : "r"(a[0]), "r"(a[1]), "r"(a[2]), "r"(a[3]), "r"(b[0]), "r"(b[1]));
}

__device__ __forceinline__ void cp16(uint32_t dst, const void* src, int sz) {
    asm volatile("cp.async.cg.shared.global [%0], [%1], 16, %2;"
                 :: "r"(dst), "l"(src), "r"(sz));
}

// BM=128 x BN=64 block tile, 8 warps (2x4), warp tile 64x16 (MT=4, NT=2).
// Double-buffered smem, cp.async staging of chunk k+1 overlaps compute of k.
// tf32 hi/lo split + (optional) relu(+bias) at fragment-load time.
template<int NOUT, bool IN_TRANS, bool PRESCALE>
__device__ __forceinline__ void gemm_tc_body(const float* __restrict__ A,
                                             const float* __restrict__ W,
                                             const float* __restrict__ b_in,
                                             float* __restrict__ T,
                                             int bx, int by)
{
    constexpr int BM = 128, BN = 64;
    constexpr int KC = 16, NK = D_K / KC;     // 8 chunks
    constexpr int AP = KC + 4;                // 20: A frag reads conflict-free
    constexpr int WP = BN + 8;                // 72: W frag reads conflict-free
    constexpr int MT = 4, NT = 2;

    __shared__ float As[2][BM][AP];           // 20.0 KB
    __shared__ float Ws[2][KC][WP];           //  9.2 KB

    const int tid   = threadIdx.x;
    const int wid   = tid >> 5;
    const int lane  = tid & 31;
    const int wm    = wid & 1;
    const int wn    = wid >> 1;
    const int group = lane >> 2;              // 0..7
    const int tig   = lane & 3;               // 0..3
    const int row0  = bx * BM;
    const int n0    = by * BN;
    const int mbase = wm * 64;
    const int nbase = wn * 16;

    float acc[MT][NT][4];
#pragma unroll
    for (int im = 0; im < MT; im++)
#pragma unroll
        for (int in = 0; in < NT; in++)
#pragma unroll
            for (int e = 0; e < 4; e++) acc[im][in][e] = 0.f;

    // ---- async stage of one (A,W) chunk into buffer buf --------------------
    auto stage = [&](int buf, int kc) {
        // A chunk: BM x KC floats = 512 float4, 2 per thread
#pragma unroll
        for (int q = 0; q < 2; q++) {
            int f  = tid + q * 256;
            int r  = f >> 2;                  // 4 float4 per row
            int k4 = f & 3;
            int gr = row0 + r;
            const float* src = &A[(size_t)clampi(gr) * D_K + kc + k4 * 4];
            uint32_t dst = (uint32_t)__cvta_generic_to_shared(&As[buf][r][k4 * 4]);
            cp16(dst, src, gr < N_NODES ? 16 : 0);   // zero-fill OOB rows
        }
        // W chunk: KC x BN floats = 256 float4, 1 per thread
        {
            int kk = tid >> 4;
            int n4 = tid & 15;
            const float* src = &W[(size_t)(kc + kk) * NOUT + n0 + n4 * 4];
            uint32_t dst = (uint32_t)__cvta_generic_to_shared(&Ws[buf][kk][n4 * 4]);
            cp16(dst, src, 16);
        }
        asm volatile("cp.async.commit_group;" ::: "memory");
    };

    stage(0, 0);
    int buf = 0;

#pragma unroll
    for (int kci = 0; kci < NK; kci++) {
        asm volatile("cp.async.wait_group 0;" ::: "memory");
        __syncthreads();                       // chunk kci ready for all warps
        if (kci + 1 < NK) stage(buf ^ 1, (kci + 1) * KC);  // overlaps compute

#pragma unroll
        for (int ks = 0; ks < KC / 8; ks++) {  // 2
            float bias0 = 0.f, bias1 = 0.f;
            if constexpr (IN_TRANS) {
                int k0 = ks * 8 + tig;
                bias0 = b_in[kci * KC + k0];
                bias1 = b_in[kci * KC + k0 + 4];
            }
            unsigned ah[MT][4], al[MT][4];
#pragma unroll
            for (int im = 0; im < MT; im++) {
#pragma unroll
                for (int e = 0; e < 4; e++) {
                    int r = mbase + im * 16 + group + (e & 1) * 8;
                    int k = ks * 8 + tig + (e >> 1) * 4;
                    float a = As[buf][r][k];
                    if constexpr (IN_TRANS)
                        a = fmaxf(a + ((e >> 1) ? bias1 : bias0), 0.f);
                    unsigned h = f2tf32(a);
                    ah[im][e] = h;
                    al[im][e] = f2tf32(a - __uint_as_float(h));
                }
            }
#pragma unroll
            for (int in = 0; in < NT; in++) {
                unsigned bh[2], bl[2];
#pragma unroll
                for (int e = 0; e < 2; e++) {
                    int k = ks * 8 + tig + e * 4;
                    int n = nbase + in * 8 + group;
                    float b = Ws[buf][k][n];
                    unsigned h = f2tf32(b);
                    bh[e] = h;
                    bl[e] = f2tf32(b - __uint_as_float(h));
                }
#pragma unroll
                for (int im = 0; im < MT; im++) {
                    mma_tf32(acc[im][in], ah[im], bh);
                    mma_tf32(acc[im][in], ah[im], bl);
                    mma_tf32(acc[im][in], al[im], bh);
                }
            }
        }
        buf ^= 1;
    }

    // ---- epilogue: optional dinv[row] prescale, store ----------------------
#pragma unroll
    for (int im = 0; im < MT; im++) {
#pragma unroll
        for (int half = 0; half < 2; half++) {
            int r = row0 + mbase + im * 16 + group + half * 8;
            if (r >= N_NODES) continue;
            float dv = PRESCALE ? g_dinv[r] : 1.0f;
#pragma unroll
            for (int in = 0; in < NT; in++) {
                float2 t;
                t.x = acc[im][in][half * 2 + 0] * dv;
                t.y = acc[im][in][half * 2 + 1] * dv;
                *(float2*)&T[(size_t)r * NOUT + n0 + nbase + in * 8 + 2 * tig] = t;
            }
        }
    }
}

// ---------------- fused: gemm1 (raw output) + degree count ------------------
#define G1_BLOCKS  ((N_NODES + 127) / 128 * 2)         // 782
#define CNT_BLOCKS ((N_EDGES + 255) / 256)             // 2344

__global__ void __launch_bounds__(256, 2)
k_gemm1_count(const float* __restrict__ x, const float* __restrict__ W1,
              const int* __restrict__ ei)
{
    int b = blockIdx.x;
    if (b < G1_BLOCKS) {
        gemm_tc_body<D_H1, false, false>(x, W1, nullptr, g_t1, b >> 1, b & 1);
    } else {
        int e = (b - G1_BLOCKS) * 256 + threadIdx.x;
        if (e < N_EDGES) atomicAdd(&g_deg[clampi(ei[N_EDGES + e])], 1);
    }
}

__global__ void __launch_bounds__(256, 2)
k_gemm2(const float* __restrict__ W2, const float* __restrict__ b1) {
    gemm_tc_body<D_H2, true, true>(g_agg1, W2, b1, g_t2, blockIdx.x, 0);
}

// ---------------- parallel 3-phase scan --------------------------------------
__global__ void k_scanA() {
    __shared__ int sh[256];
    int t = threadIdx.x;
    int n = blockIdx.x * 256 + t;
    sh[t] = (n < N_NODES) ? g_deg[n] : 0;
    __syncthreads();
#pragma unroll
    for (int off = 128; off; off >>= 1) {
        if (t < off) sh[t] += sh[t + off];
        __syncthreads();
    }
    if (t == 0) g_bsum[blockIdx.x] = sh[0];
}

__global__ void k_scanB() {
    __shared__ int sh[256];
    int t = threadIdx.x;
    int v = (t < SCAN_NB) ? g_bsum[t] : 0;
    sh[t] = v;
    __syncthreads();
    for (int off = 1; off < 256; off <<= 1) {
        int add = (t >= off) ? sh[t - off] : 0;
        __syncthreads();
        sh[t] += add;
        __syncthreads();
    }
    if (t < SCAN_NB) g_bsum[t] = sh[t] - v;            // exclusive
    if (t == 255) g_rowstart[N_NODES] = sh[255];       // total == N_EDGES
}

__global__ void k_scanC() {
    __shared__ int sh[256];
    int t = threadIdx.x;
    int n = blockIdx.x * 256 + t;
    int d = (n < N_NODES) ? g_deg[n] : 0;
    sh[t] = d;
    __syncthreads();
    for (int off = 1; off < 256; off <<= 1) {
        int add = (t >= off) ? sh[t - off] : 0;
        __syncthreads();
        sh[t] += add;
        __syncthreads();
    }
    if (n < N_NODES) {
        int run = g_bsum[blockIdx.x] + sh[t] - d;      // exclusive prefix
        g_rowstart[n] = run;
        g_cursor[n]   = run;
        g_dinv[n]     = rsqrtf((float)(d + 1));        // +1 self-loop
        g_deg[n]      = 0;                             // restore zero
    }
}

// ---------------- CSR fill (src only) ---------------------------------------
__global__ void k_fill(const int* __restrict__ ei) {
    int e = blockIdx.x * blockDim.x + threadIdx.x;
    if (e >= N_EDGES) return;
    int src = clampi(ei[e]);
    int dst = clampi(ei[N_EDGES + e]);
    int pos = atomicAdd(&g_cursor[dst], 1);
    g_csr_src[pos] = src;
}

// ---------------- layer-1 aggregate: t1 raw, per-edge dinv[src] -------------
__global__ void k_agg1() {
    int n    = (blockIdx.x * blockDim.x + threadIdx.x) >> 5;
    int lane = threadIdx.x & 31;
    if (n >= N_NODES) return;

    int   s0 = g_rowstart[n];
    int   s1 = g_rowstart[n + 1];
    float dv = g_dinv[n];

    float4 acc = *(const float4*)&g_t1[(size_t)n * D_H1 + lane * 4];
    acc.x *= dv; acc.y *= dv; acc.z *= dv; acc.w *= dv;

    int e = s0;
    for (; e + 1 < s1; e += 2) {
        int srcA = g_csr_src[e];
        int srcB = g_csr_src[e + 1];
        float nmA = g_dinv[srcA];
        float nmB = g_dinv[srcB];
        float4 vA = *(const float4*)&g_t1[(size_t)srcA * D_H1 + lane * 4];
        float4 vB = *(const float4*)&g_t1[(size_t)srcB * D_H1 + lane * 4];
        acc.x = fmaf(vA.x, nmA, acc.x);
        acc.y = fmaf(vA.y, nmA, acc.y);
        acc.z = fmaf(vA.z, nmA, acc.z);
        acc.w = fmaf(vA.w, nmA, acc.w);
        acc.x = fmaf(vB.x, nmB, acc.x);
        acc.y = fmaf(vB.y, nmB, acc.y);
        acc.z = fmaf(vB.z, nmB, acc.z);
        acc.w = fmaf(vB.w, nmB, acc.w);
    }
    if (e < s1) {
        int src = g_csr_src[e];
        float nm = g_dinv[src];
        float4 v = *(const float4*)&g_t1[(size_t)src * D_H1 + lane * 4];
        acc.x = fmaf(v.x, nm, acc.x);
        acc.y = fmaf(v.y, nm, acc.y);
        acc.z = fmaf(v.z, nm, acc.z);
        acc.w = fmaf(v.w, nm, acc.w);
    }
    acc.x *= dv; acc.y *= dv; acc.z *= dv; acc.w *= dv;
    *(float4*)&g_agg1[(size_t)n * D_H1 + lane * 4] = acc;
}

// ---------------- layer-2 aggregate (t2 prescaled) + final GEMV -------------
__global__ void k_agg2_final(const float* __restrict__ b2,
                             const float* __restrict__ W3,
                             const float* __restrict__ b3,
                             float* __restrict__ out)
{
    int n    = (blockIdx.x * blockDim.x + threadIdx.x) >> 5;
    int lane = threadIdx.x & 31;
    if (n >= N_NODES) return;

    int   s0 = g_rowstart[n];
    int   s1 = g_rowstart[n + 1];
    float dv = g_dinv[n];

    float2 acc = *(const float2*)&g_t2[(size_t)n * D_H2 + lane * 2];

    int e = s0;
    for (; e + 1 < s1; e += 2) {
        int srcA = g_csr_src[e];
        int srcB = g_csr_src[e + 1];
        float2 vA = *(const float2*)&g_t2[(size_t)srcA * D_H2 + lane * 2];
        float2 vB = *(const float2*)&g_t2[(size_t)srcB * D_H2 + lane * 2];
        acc.x += vA.x + vB.x;
        acc.y += vA.y + vB.y;
    }
    if (e < s1) {
        int src = g_csr_src[e];
        float2 v = *(const float2*)&g_t2[(size_t)src * D_H2 + lane * 2];
        acc.x += v.x; acc.y += v.y;
    }
    acc.x *= dv; acc.y *= dv;

    float2 bb = *(const float2*)&b2[lane * 2];
    float2 w  = *(const float2*)&W3[lane * 2];
    float h0 = fmaxf(acc.x + bb.x, 0.f);
    float h1 = fmaxf(acc.y + bb.y, 0.f);
    float s  = fmaf(h0, w.x, h1 * w.y);
#pragma unroll
    for (int o = 16; o; o >>= 1) s += __shfl_xor_sync(0xffffffffu, s, o);
    if (lane == 0) out[n] = s + b3[0];
}

// ---------------- launch (single stream) ------------------------------------
extern "C" void kernel_launch(void* const* d_in, const int* in_sizes, int n_in,
                              void* d_out, int out_size)
{
    const float* x  = (const float*)d_in[0];
    const int*   ei = (const int*)d_in[1];     // int32 edge_index
    const float* W1 = (const float*)d_in[2];
    const float* b1 = (const float*)d_in[3];
    const float* W2 = (const float*)d_in[4];
    const float* b2 = (const float*)d_in[5];
    const float* W3 = (const float*)d_in[6];
    const float* b3 = (const float*)d_in[7];
    float*       out = (float*)d_out;
    (void)in_sizes; (void)n_in; (void)out_size;

    k_gemm1_count<<<G1_BLOCKS + CNT_BLOCKS, 256>>>(x, W1, ei);  // 1
    k_scanA      <<<SCAN_NB, 256>>>();                           // 2
    k_scanB      <<<1, 256>>>();                                 // 3
    k_scanC      <<<SCAN_NB, 256>>>();                           // 4 (profiled)
    k_fill       <<<(N_EDGES + 255) / 256, 256>>>(ei);           // 5
    k_agg1       <<<(N_NODES * 32 + 255) / 256, 256>>>();        // 6
    k_gemm2      <<<(N_NODES + 127) / 128, 256>>>(W2, b1);       // 7
    k_agg2_final <<<(N_NODES * 32 + 255) / 256, 256>>>(b2, W3, b3, out);
}

// round 15
// speedup vs baseline: 2.0251x; 1.0003x over previous
#include <cuda_runtime.h>
#include <cstdint>

#define N_NODES 50000
#define N_EDGES 600000
#define D_K     128
#define D_H1    128
#define D_H2    64

#define SCAN_NB ((N_NODES + 255) / 256)                // 196

// ---------------- scratch (device globals: no allocation allowed) ----------
// g_deg is zero at module load and re-zeroed by k_scanBC each run (invariant).
__device__ int   g_deg     [N_NODES];
__device__ float g_dinv    [N_NODES];
__device__ int   g_bsum    [SCAN_NB];
__device__ int   g_rowstart[N_NODES + 1];
__device__ int   g_cursor  [N_NODES];
__device__ int   g_csr_src [N_EDGES];
__device__ __align__(16) float g_t1  [N_NODES * D_H1];   // x @ W1 (raw)
__device__ __align__(16) float g_agg1[N_NODES * D_H1];   // aggregated layer-1
__device__ __align__(16) float g_t2  [N_NODES * D_H2];   // (relu(agg1+b1) @ W2) * dinv

__device__ __forceinline__ int clampi(int v) {
    return min(max(v, 0), N_NODES - 1);
}

// ---------------- tensor-core GEMM (3xTF32) helpers --------------------------
__device__ __forceinline__ unsigned f2tf32(float x) {
    unsigned r;
    asm("cvt.rna.tf32.f32 %0, %1;" : "=r"(r) : "f"(x));
    return r;
}

__device__ __forceinline__ void mma_tf32(float* d, const unsigned* a, const unsigned* b) {
    asm volatile(
        "mma.sync.aligned.m16n8k8.row.col.f32.tf32.tf32.f32 "
        "{%0,%1,%2,%3}, {%4,%5,%6,%7}, {%8,%9}, {%0,%1,%2,%3};"
        : "+f"(d[0]), "+f"(d[1]), "+f"(d[2]), "+f"(d[3])
        : "r"(a[0]), "r"(a[1]), "r"(a[2]), "r"(a[3]), "r"(b[0]), "r"(b[1]));
}

__device__ __forceinline__ void cp16(uint32_t dst, const void* src, int sz) {
    asm volatile("cp.async.cg.shared.global [%0], [%1], 16, %2;"
                 :: "r"(dst), "l"(src), "r"(sz));
}

// BM=128 x BN=64 block tile, 8 warps (2x4), warp tile 64x16 (MT=4, NT=2).
// Double-buffered smem, cp.async staging of chunk k+1 overlaps compute of k.
template<int NOUT, bool IN_TRANS, bool PRESCALE>
__device__ __forceinline__ void gemm_tc_body(const float* __restrict__ A,
                                             const float* __restrict__ W,
                                             const float* __restrict__ b_in,
                                             float* __restrict__ T,
                                             int bx, int by)
{
    constexpr int BM = 128, BN = 64;
    constexpr int KC = 16, NK = D_K / KC;     // 8 chunks
    constexpr int AP = KC + 4;                // 20
    constexpr int WP = BN + 8;                // 72
    constexpr int MT = 4, NT = 2;

    __shared__ float As[2][BM][AP];           // 20.0 KB
    __shared__ float Ws[2][KC][WP];           //  9.2 KB

    const int tid   = threadIdx.x;
    const int wid   = tid >> 5;
    const int lane  = tid & 31;
    const int wm    = wid & 1;
    const int wn    = wid >> 1;
    const int group = lane >> 2;              // 0..7
    const int tig   = lane & 3;               // 0..3
    const int row0  = bx * BM;
    const int n0    = by * BN;
    const int mbase = wm * 64;
    const int nbase = wn * 16;

    float acc[MT][NT][4];
#pragma unroll
    for (int im = 0; im < MT; im++)
#pragma unroll
        for (int in = 0; in < NT; in++)
#pragma unroll
            for (int e = 0; e < 4; e++) acc[im][in][e] = 0.f;

    auto stage = [&](int buf, int kc) {
#pragma unroll
        for (int q = 0; q < 2; q++) {
            int f  = tid + q * 256;
            int r  = f >> 2;
            int k4 = f & 3;
            int gr = row0 + r;
            const float* src = &A[(size_t)clampi(gr) * D_K + kc + k4 * 4];
            uint32_t dst = (uint32_t)__cvta_generic_to_shared(&As[buf][r][k4 * 4]);
            cp16(dst, src, gr < N_NODES ? 16 : 0);
        }
        {
            int kk = tid >> 4;
            int n4 = tid & 15;
            const float* src = &W[(size_t)(kc + kk) * NOUT + n0 + n4 * 4];
            uint32_t dst = (uint32_t)__cvta_generic_to_shared(&Ws[buf][kk][n4 * 4]);
            cp16(dst, src, 16);
        }
        asm volatile("cp.async.commit_group;" ::: "memory");
    };

    stage(0, 0);
    int buf = 0;

#pragma unroll
    for (int kci = 0; kci < NK; kci++) {
        asm volatile("cp.async.wait_group 0;" ::: "memory");
        __syncthreads();
        if (kci + 1 < NK) stage(buf ^ 1, (kci + 1) * KC);

#pragma unroll
        for (int ks = 0; ks < KC / 8; ks++) {
            float bias0 = 0.f, bias1 = 0.f;
            if constexpr (IN_TRANS) {
                int k0 = ks * 8 + tig;
                bias0 = b_in[kci * KC + k0];
                bias1 = b_in[kci * KC + k0 + 4];
            }
            unsigned ah[MT][4], al[MT][4];
#pragma unroll
            for (int im = 0; im < MT; im++) {
#pragma unroll
                for (int e = 0; e < 4; e++) {
                    int r = mbase + im * 16 + group + (e & 1) * 8;
                    int k = ks * 8 + tig + (e >> 1) * 4;
                    float a = As[buf][r][k];
                    if constexpr (IN_TRANS)
                        a = fmaxf(a + ((e >> 1) ? bias1 : bias0), 0.f);
                    unsigned h = f2tf32(a);
                    ah[im][e] = h;
                    al[im][e] = f2tf32(a - __uint_as_float(h));
                }
            }
#pragma unroll
            for (int in = 0; in < NT; in++) {
                unsigned bh[2], bl[2];
#pragma unroll
                for (int e = 0; e < 2; e++) {
                    int k = ks * 8 + tig + e * 4;
                    int n = nbase + in * 8 + group;
                    float b = Ws[buf][k][n];
                    unsigned h = f2tf32(b);
                    bh[e] = h;
                    bl[e] = f2tf32(b - __uint_as_float(h));
                }
#pragma unroll
                for (int im = 0; im < MT; im++) {
                    mma_tf32(acc[im][in], ah[im], bh);
                    mma_tf32(acc[im][in], ah[im], bl);
                    mma_tf32(acc[im][in], al[im], bh);
                }
            }
        }
        buf ^= 1;
    }

#pragma unroll
    for (int im = 0; im < MT; im++) {
#pragma unroll
        for (int half = 0; half < 2; half++) {
            int r = row0 + mbase + im * 16 + group + half * 8;
            if (r >= N_NODES) continue;
            float dv = PRESCALE ? g_dinv[r] : 1.0f;
#pragma unroll
            for (int in = 0; in < NT; in++) {
                float2 t;
                t.x = acc[im][in][half * 2 + 0] * dv;
                t.y = acc[im][in][half * 2 + 1] * dv;
                *(float2*)&T[(size_t)r * NOUT + n0 + nbase + in * 8 + 2 * tig] = t;
            }
        }
    }
}

// ---------------- fused launches: gemm1 split in column halves --------------
// half A (by=0) carries the degree count; half B (by=1) carries the CSR fill.
// Deps: count -> scans -> fill; gemm1 halves depend only on inputs; agg1
// follows halfB+fill. Both atomic kernels ride inside GEMM launches.
#define G1H_BLOCKS ((N_NODES + 127) / 128)             // 391
#define EDG_BLOCKS ((N_EDGES + 255) / 256)             // 2344

__global__ void __launch_bounds__(256, 2)
k_g1a_count(const float* __restrict__ x, const float* __restrict__ W1,
            const int* __restrict__ ei)
{
    int b = blockIdx.x;
    if (b < G1H_BLOCKS) {
        gemm_tc_body<D_H1, false, false>(x, W1, nullptr, g_t1, b, 0);
    } else {
        int e = (b - G1H_BLOCKS) * 256 + threadIdx.x;
        if (e < N_EDGES) atomicAdd(&g_deg[clampi(ei[N_EDGES + e])], 1);
    }
}

__global__ void __launch_bounds__(256, 2)
k_g1b_fill(const float* __restrict__ x, const float* __restrict__ W1,
           const int* __restrict__ ei)
{
    int b = blockIdx.x;
    if (b < G1H_BLOCKS) {
        gemm_tc_body<D_H1, false, false>(x, W1, nullptr, g_t1, b, 1);
    } else {
        int e = (b - G1H_BLOCKS) * 256 + threadIdx.x;
        if (e < N_EDGES) {
            int src = clampi(ei[e]);
            int dst = clampi(ei[N_EDGES + e]);
            int pos = atomicAdd(&g_cursor[dst], 1);
            g_csr_src[pos] = src;
        }
    }
}

__global__ void __launch_bounds__(256, 2)
k_gemm2(const float* __restrict__ W2, const float* __restrict__ b1) {
    gemm_tc_body<D_H2, true, true>(g_agg1, W2, b1, g_t2, blockIdx.x, 0);
}

// ---------------- scan phase A: per-block sums -------------------------------
__global__ void k_scanA() {
    __shared__ int sh[256];
    int t = threadIdx.x;
    int n = blockIdx.x * 256 + t;
    sh[t] = (n < N_NODES) ? g_deg[n] : 0;
    __syncthreads();
#pragma unroll
    for (int off = 128; off; off >>= 1) {
        if (t < off) sh[t] += sh[t + off];
        __syncthreads();
    }
    if (t == 0) g_bsum[blockIdx.x] = sh[0];
}

// ---------------- scan phase B+C fused: every block re-scans block sums -----
__global__ void k_scanBC() {
    __shared__ int bs[256];
    __shared__ int sh[256];
    int t = threadIdx.x;

    int bsv = (t < SCAN_NB) ? g_bsum[t] : 0;
    bs[t] = bsv;
    int n = blockIdx.x * 256 + t;
    int d = (n < N_NODES) ? g_deg[n] : 0;
    sh[t] = d;
    __syncthreads();

    for (int off = 1; off < 256; off <<= 1) {
        int addb = (t >= off) ? bs[t - off] : 0;
        int adds = (t >= off) ? sh[t - off] : 0;
        __syncthreads();
        bs[t] += addb;
        sh[t] += adds;
        __syncthreads();
    }

    // exclusive block base for this block
    int my_bsum;
    if (t == 0) {
        // reload this block's own sum to form exclusive prefix
        my_bsum = g_bsum[blockIdx.x];
    }
    __syncthreads();
    int block_base = bs[blockIdx.x] - ((t == t) ? 0 : 0);  // inclusive incl. own
    // convert to exclusive: subtract this block's own sum
    block_base -= g_bsum[blockIdx.x];
    (void)my_bsum;

    if (n < N_NODES) {
        int run = block_base + sh[t] - d;      // exclusive prefix
        g_rowstart[n] = run;
        g_cursor[n]   = run;
        g_dinv[n]     = rsqrtf((float)(d + 1));  // +1 self-loop
        g_deg[n]      = 0;                        // restore zero
    }
    if (blockIdx.x == 0 && t == 255)
        g_rowstart[N_NODES] = bs[255];            // total == N_EDGES
}

// ---------------- layer-1 aggregate: t1 raw, per-edge dinv[src] -------------
__global__ void k_agg1() {
    int n    = (blockIdx.x * blockDim.x + threadIdx.x) >> 5;
    int lane = threadIdx.x & 31;
    if (n >= N_NODES) return;

    int   s0 = g_rowstart[n];
    int   s1 = g_rowstart[n + 1];
    float dv = g_dinv[n];

    float4 acc = *(const float4*)&g_t1[(size_t)n * D_H1 + lane * 4];
    acc.x *= dv; acc.y *= dv; acc.z *= dv; acc.w *= dv;

    int e = s0;
    for (; e + 1 < s1; e += 2) {
        int srcA = g_csr_src[e];
        int srcB = g_csr_src[e + 1];
        float nmA = g_dinv[srcA];
        float nmB = g_dinv[srcB];
        float4 vA = *(const float4*)&g_t1[(size_t)srcA * D_H1 + lane * 4];
        float4 vB = *(const float4*)&g_t1[(size_t)srcB * D_H1 + lane * 4];
        acc.x = fmaf(vA.x, nmA, acc.x);
        acc.y = fmaf(vA.y, nmA, acc.y);
        acc.z = fmaf(vA.z, nmA, acc.z);
        acc.w = fmaf(vA.w, nmA, acc.w);
        acc.x = fmaf(vB.x, nmB, acc.x);
        acc.y = fmaf(vB.y, nmB, acc.y);
        acc.z = fmaf(vB.z, nmB, acc.z);
        acc.w = fmaf(vB.w, nmB, acc.w);
    }
    if (e < s1) {
        int src = g_csr_src[e];
        float nm = g_dinv[src];
        float4 v = *(const float4*)&g_t1[(size_t)src * D_H1 + lane * 4];
        acc.x = fmaf(v.x, nm, acc.x);
        acc.y = fmaf(v.y, nm, acc.y);
        acc.z = fmaf(v.z, nm, acc.z);
        acc.w = fmaf(v.w, nm, acc.w);
    }
    acc.x *= dv; acc.y *= dv; acc.z *= dv; acc.w *= dv;
    *(float4*)&g_agg1[(size_t)n * D_H1 + lane * 4] = acc;
}

// ---------------- layer-2 aggregate (t2 prescaled) + final GEMV -------------
__global__ void k_agg2_final(const float* __restrict__ b2,
                             const float* __restrict__ W3,
                             const float* __restrict__ b3,
                             float* __restrict__ out)
{
    int n    = (blockIdx.x * blockDim.x + threadIdx.x) >> 5;
    int lane = threadIdx.x & 31;
    if (n >= N_NODES) return;

    int   s0 = g_rowstart[n];
    int   s1 = g_rowstart[n + 1];
    float dv = g_dinv[n];

    float2 acc = *(const float2*)&g_t2[(size_t)n * D_H2 + lane * 2];

    int e = s0;
    for (; e + 1 < s1; e += 2) {
        int srcA = g_csr_src[e];
        int srcB = g_csr_src[e + 1];
        float2 vA = *(const float2*)&g_t2[(size_t)srcA * D_H2 + lane * 2];
        float2 vB = *(const float2*)&g_t2[(size_t)srcB * D_H2 + lane * 2];
        acc.x += vA.x + vB.x;
        acc.y += vA.y + vB.y;
    }
    if (e < s1) {
        int src = g_csr_src[e];
        float2 v = *(const float2*)&g_t2[(size_t)src * D_H2 + lane * 2];
        acc.x += v.x; acc.y += v.y;
    }
    acc.x *= dv; acc.y *= dv;

    float2 bb = *(const float2*)&b2[lane * 2];
    float2 w  = *(const float2*)&W3[lane * 2];
    float h0 = fmaxf(acc.x + bb.x, 0.f);
    float h1 = fmaxf(acc.y + bb.y, 0.f);
    float s  = fmaf(h0, w.x, h1 * w.y);
#pragma unroll
    for (int o = 16; o; o >>= 1) s += __shfl_xor_sync(0xffffffffu, s, o);
    if (lane == 0) out[n] = s + b3[0];
}

// ---------------- launch (single stream) ------------------------------------
extern "C" void kernel_launch(void* const* d_in, const int* in_sizes, int n_in,
                              void* d_out, int out_size)
{
    const float* x  = (const float*)d_in[0];
    const int*   ei = (const int*)d_in[1];     // int32 edge_index
    const float* W1 = (const float*)d_in[2];
    const float* b1 = (const float*)d_in[3];
    const float* W2 = (const float*)d_in[4];
    const float* b2 = (const float*)d_in[5];
    const float* W3 = (const float*)d_in[6];
    const float* b3 = (const float*)d_in[7];
    float*       out = (float*)d_out;
    (void)in_sizes; (void)n_in; (void)out_size;

    k_g1a_count <<<G1H_BLOCKS + EDG_BLOCKS, 256>>>(x, W1, ei);  // 1: gemm1a + count
    k_scanA     <<<SCAN_NB, 256>>>();                            // 2
    k_scanBC    <<<SCAN_NB, 256>>>();                            // 3
    k_g1b_fill  <<<G1H_BLOCKS + EDG_BLOCKS, 256>>>(x, W1, ei);  // 4: gemm1b + fill
    k_agg1      <<<(N_NODES * 32 + 255) / 256, 256>>>();         // 5
    k_gemm2     <<<(N_NODES + 127) / 128, 256>>>(W2, b1);        // 6
    k_agg2_final<<<(N_NODES * 32 + 255) / 256, 256>>>(b2, W3, b3, out);
}